// round 7
// baseline (speedup 1.0000x reference)
#include <cuda_runtime.h>
#include <cstdint>

// Problem-fixed sizes
#define MAXN   50000
#define MAXE   800000
#define F1     128
#define F2     64

// ---------- static scratch (module-load allocation; no runtime allocs) ----------
__device__ int   g_is64;                // 1 if edge_index stored as int64
__device__ int   g_src   [MAXE];        // normalized src indices (int32)
__device__ int   g_dst   [MAXE];        // normalized dst indices (int32)
__device__ int   g_cnt   [MAXN];        // in-degree histogram
__device__ int   g_rowptr[MAXN + 1];    // CSR row pointers (by dst)
__device__ int   g_cur   [MAXN];        // write cursors for binning
__device__ int   g_eidx  [MAXE];        // src node per CSR slot
__device__ float g_rdeg  [MAXN];        // 1/max(deg,1)
__device__ float g_agg1  [MAXN * F1];   // mean_{src->i} x[src]  (rdeg folded in)
__device__ float g_h     [MAXN * F1];   // relu(mean@W1_l + b1 + x@W1_r)
__device__ float g_p     [MAXN * F2];   // h @ W2_l  (gathered in layer 2)
__device__ float g_q     [MAXN * F2];   // h @ W2_r

// ============================================================
// 0a. detect edge_index dtype.
//     int64 little-endian node ids < 2^31 -> every odd int32 word is 0.
//     64 consecutive random ids in [0,50000) are never all zero.
// ============================================================
__global__ void k_detect(const int* __restrict__ ei32) {
    if (threadIdx.x == 0 && blockIdx.x == 0) {
        int all0 = 1;
        for (int i = 1; i < 128; i += 2)
            if (ei32[i] != 0) { all0 = 0; break; }
        g_is64 = all0;
    }
}

// ============================================================
// 0b. normalize edge list to int32 src/dst arrays + zero histogram
// ============================================================
__global__ __launch_bounds__(256)
void k_convert(const int* __restrict__ ei32, int E, int n) {
    int e = blockIdx.x * blockDim.x + threadIdx.x;
    if (e < n) g_cnt[e] = 0;
    if (e >= E) return;
    if (g_is64) {
        g_src[e] = ei32[2 * e];               // low word of int64
        g_dst[e] = ei32[2 * (E + e)];
    } else {
        g_src[e] = ei32[e];
        g_dst[e] = ei32[E + e];
    }
}

// ============================================================
// 1. histogram of dst (int atomics only)
// ============================================================
__global__ __launch_bounds__(256)
void k_hist(int E) {
    int e = blockIdx.x * blockDim.x + threadIdx.x;
    if (e >= E) return;
    int dst = g_dst[e];
    if ((unsigned)dst < (unsigned)MAXN)       // guard: degrade, don't trap
        atomicAdd(&g_cnt[dst], 1);
}

// ============================================================
// 2. exclusive scan (single block, 1024 thr) -> rowptr, cur, rdeg
// ============================================================
__global__ __launch_bounds__(1024)
void k_scan(int n) {
    __shared__ int wsum[32];
    __shared__ int stotal;
    int tid  = threadIdx.x;
    int lane = tid & 31, wid = tid >> 5;
    int running = 0;

    for (int base = 0; base < n; base += 1024) {
        int idx = base + tid;
        int v = (idx < n) ? g_cnt[idx] : 0;

        // inclusive warp scan
        int s = v;
#pragma unroll
        for (int o = 1; o < 32; o <<= 1) {
            int t = __shfl_up_sync(0xFFFFFFFFu, s, o);
            if (lane >= o) s += t;
        }
        if (lane == 31) wsum[wid] = s;
        __syncthreads();
        if (wid == 0) {
            int w = wsum[lane];
#pragma unroll
            for (int o = 1; o < 32; o <<= 1) {
                int t = __shfl_up_sync(0xFFFFFFFFu, w, o);
                if (lane >= o) w += t;
            }
            wsum[lane] = w;                 // inclusive warp sums
            if (lane == 31) stotal = w;
        }
        __syncthreads();
        int woff = (wid == 0) ? 0 : wsum[wid - 1];
        int excl = running + woff + (s - v);
        if (idx < n) {
            g_rowptr[idx] = excl;
            g_cur[idx]    = excl;
            g_rdeg[idx]   = 1.0f / fmaxf((float)v, 1.0f);
        }
        running += stotal;
        __syncthreads();                    // protect wsum before next iter
    }
    if (tid == 0) g_rowptr[n] = running;    // == E (if all dst in range)
}

// ============================================================
// 3. bin edges into CSR (int atomics only)
// ============================================================
__global__ __launch_bounds__(256)
void k_bin(int E) {
    int e = blockIdx.x * blockDim.x + threadIdx.x;
    if (e >= E) return;
    int src = g_src[e];
    int dst = g_dst[e];
    if ((unsigned)dst >= (unsigned)MAXN) return;
    int pos = atomicAdd(&g_cur[dst], 1);
    if ((unsigned)pos < (unsigned)MAXE)
        g_eidx[pos] = src;
}

// ============================================================
// 4. gather-aggregate layer 1: agg1[i] = rdeg[i] * sum x[src]
//    one warp per node; lane c owns float4 channel chunk c
// ============================================================
__global__ __launch_bounds__(256)
void k_agg1(const float* __restrict__ x, int n) {
    int t = blockIdx.x * blockDim.x + threadIdx.x;
    int node = t >> 5;
    if (node >= n) return;
    int c = t & 31;

    int beg = g_rowptr[node], end = g_rowptr[node + 1];
    float4 s = make_float4(0.f, 0.f, 0.f, 0.f);
    const float4* x4 = reinterpret_cast<const float4*>(x);
    for (int e = beg; e < end; e++) {
        int src = g_eidx[e];
        float4 v = x4[(size_t)src * 32 + c];
        s.x += v.x; s.y += v.y; s.z += v.z; s.w += v.w;
    }
    float r = g_rdeg[node];
    s.x *= r; s.y *= r; s.z *= r; s.w *= r;
    reinterpret_cast<float4*>(g_agg1)[(size_t)node * 32 + c] = s;
}

// ============================================================
// 5. GEMM1: h = relu([agg1 | x] @ [W1_l ; W1_r] + b1)
//    M x 128, K = 256.  BM=128, BN=128, BK=16, 256 thr, 8x8/thr
// ============================================================
__global__ __launch_bounds__(256)
void k_gemm1(const float* __restrict__ x,
             const float* __restrict__ W1l,
             const float* __restrict__ b1,
             const float* __restrict__ W1r, int M) {
    __shared__ float As[16][132];   // [k][m], padded
    __shared__ float Bs[16][128];   // [k][n]

    int tid  = threadIdx.x;
    int row0 = blockIdx.x * 128;

    float acc[8][8];
#pragma unroll
    for (int i = 0; i < 8; i++)
#pragma unroll
        for (int j = 0; j < 8; j++) acc[i][j] = 0.f;

    int tr = tid >> 4;   // 0..15 row group
    int tc = tid & 15;   // 0..15 col group

    for (int kt = 0; kt < 16; kt++) {           // K = 256 in 16-chunks
        // ---- load A (512 float4 slots; 2 per thread) ----
#pragma unroll
        for (int l = 0; l < 2; l++) {
            int s  = tid * 2 + l;
            int r  = s >> 2;
            int kq = s & 3;
            int rg = row0 + r;
            int kg = kt * 16 + kq * 4;
            float4 v = make_float4(0.f, 0.f, 0.f, 0.f);
            if (rg < M) {
                if (kt < 8)
                    v = *reinterpret_cast<const float4*>(g_agg1 + (size_t)rg * F1 + kg);
                else
                    v = *reinterpret_cast<const float4*>(x + (size_t)rg * F1 + (kg - 128));
            }
            As[kq * 4 + 0][r] = v.x;
            As[kq * 4 + 1][r] = v.y;
            As[kq * 4 + 2][r] = v.z;
            As[kq * 4 + 3][r] = v.w;
        }
        // ---- load B (512 float4 slots; 2 per thread) ----
#pragma unroll
        for (int l = 0; l < 2; l++) {
            int s  = tid * 2 + l;
            int k  = s >> 5;
            int c4 = s & 31;
            int kg = kt * 16 + k;
            const float* Wsrc = (kt < 8) ? (W1l + kg * 128) : (W1r + (kg - 128) * 128);
            *reinterpret_cast<float4*>(&Bs[k][c4 * 4]) =
                *reinterpret_cast<const float4*>(Wsrc + c4 * 4);
        }
        __syncthreads();

#pragma unroll
        for (int k = 0; k < 16; k++) {
            float a[8], b[8];
            *reinterpret_cast<float4*>(a)     = *reinterpret_cast<const float4*>(&As[k][tr * 8]);
            *reinterpret_cast<float4*>(a + 4) = *reinterpret_cast<const float4*>(&As[k][tr * 8 + 4]);
            *reinterpret_cast<float4*>(b)     = *reinterpret_cast<const float4*>(&Bs[k][tc * 8]);
            *reinterpret_cast<float4*>(b + 4) = *reinterpret_cast<const float4*>(&Bs[k][tc * 8 + 4]);
#pragma unroll
            for (int i = 0; i < 8; i++)
#pragma unroll
                for (int j = 0; j < 8; j++) acc[i][j] += a[i] * b[j];
        }
        __syncthreads();
    }

    // epilogue: + bias, relu, store h
    float bb[8];
#pragma unroll
    for (int j = 0; j < 8; j++) bb[j] = b1[tc * 8 + j];
#pragma unroll
    for (int i = 0; i < 8; i++) {
        int rg = row0 + tr * 8 + i;
        if (rg >= M) continue;
        float4 v0, v1;
        v0.x = fmaxf(acc[i][0] + bb[0], 0.f);
        v0.y = fmaxf(acc[i][1] + bb[1], 0.f);
        v0.z = fmaxf(acc[i][2] + bb[2], 0.f);
        v0.w = fmaxf(acc[i][3] + bb[3], 0.f);
        v1.x = fmaxf(acc[i][4] + bb[4], 0.f);
        v1.y = fmaxf(acc[i][5] + bb[5], 0.f);
        v1.z = fmaxf(acc[i][6] + bb[6], 0.f);
        v1.w = fmaxf(acc[i][7] + bb[7], 0.f);
        *reinterpret_cast<float4*>(g_h + (size_t)rg * F1 + tc * 8)     = v0;
        *reinterpret_cast<float4*>(g_h + (size_t)rg * F1 + tc * 8 + 4) = v1;
    }
}

// ============================================================
// 6. GEMM2: [p | q] = h @ [W2_l | W2_r]   (M x 128, K = 128)
// ============================================================
__global__ __launch_bounds__(256)
void k_gemm2(const float* __restrict__ W2l,
             const float* __restrict__ W2r, int M) {
    __shared__ float As[16][132];
    __shared__ float Bs[16][128];

    int tid  = threadIdx.x;
    int row0 = blockIdx.x * 128;

    float acc[8][8];
#pragma unroll
    for (int i = 0; i < 8; i++)
#pragma unroll
        for (int j = 0; j < 8; j++) acc[i][j] = 0.f;

    int tr = tid >> 4;
    int tc = tid & 15;

    for (int kt = 0; kt < 8; kt++) {            // K = 128
#pragma unroll
        for (int l = 0; l < 2; l++) {
            int s  = tid * 2 + l;
            int r  = s >> 2;
            int kq = s & 3;
            int rg = row0 + r;
            int kg = kt * 16 + kq * 4;
            float4 v = make_float4(0.f, 0.f, 0.f, 0.f);
            if (rg < M)
                v = *reinterpret_cast<const float4*>(g_h + (size_t)rg * F1 + kg);
            As[kq * 4 + 0][r] = v.x;
            As[kq * 4 + 1][r] = v.y;
            As[kq * 4 + 2][r] = v.z;
            As[kq * 4 + 3][r] = v.w;
        }
#pragma unroll
        for (int l = 0; l < 2; l++) {
            int s   = tid * 2 + l;
            int k   = s >> 5;
            int c4  = s & 31;
            int kg  = kt * 16 + k;
            int col = c4 * 4;
            const float* Wsrc = (col < 64) ? (W2l + kg * 64 + col)
                                           : (W2r + kg * 64 + (col - 64));
            *reinterpret_cast<float4*>(&Bs[k][col]) =
                *reinterpret_cast<const float4*>(Wsrc);
        }
        __syncthreads();

#pragma unroll
        for (int k = 0; k < 16; k++) {
            float a[8], b[8];
            *reinterpret_cast<float4*>(a)     = *reinterpret_cast<const float4*>(&As[k][tr * 8]);
            *reinterpret_cast<float4*>(a + 4) = *reinterpret_cast<const float4*>(&As[k][tr * 8 + 4]);
            *reinterpret_cast<float4*>(b)     = *reinterpret_cast<const float4*>(&Bs[k][tc * 8]);
            *reinterpret_cast<float4*>(b + 4) = *reinterpret_cast<const float4*>(&Bs[k][tc * 8 + 4]);
#pragma unroll
            for (int i = 0; i < 8; i++)
#pragma unroll
                for (int j = 0; j < 8; j++) acc[i][j] += a[i] * b[j];
        }
        __syncthreads();
    }

    // cols [0,64) -> p ; cols [64,128) -> q (split lands exactly at tc==8)
    float* dst = (tc < 8) ? g_p : g_q;
    int    cb  = (tc < 8) ? tc * 8 : tc * 8 - 64;
#pragma unroll
    for (int i = 0; i < 8; i++) {
        int rg = row0 + tr * 8 + i;
        if (rg >= M) continue;
        float4 v0, v1;
        v0.x = acc[i][0]; v0.y = acc[i][1]; v0.z = acc[i][2]; v0.w = acc[i][3];
        v1.x = acc[i][4]; v1.y = acc[i][5]; v1.z = acc[i][6]; v1.w = acc[i][7];
        *reinterpret_cast<float4*>(dst + (size_t)rg * F2 + cb)     = v0;
        *reinterpret_cast<float4*>(dst + (size_t)rg * F2 + cb + 4) = v1;
    }
}

// ============================================================
// 7. gather layer 2 + final epilogue:
//    out[i] = rdeg[i]*sum p[src] + b2 + q[i]
//    half-warp per node; lane c<16 owns float4 chunk c
// ============================================================
__global__ __launch_bounds__(256)
void k_aggfinal(const float* __restrict__ b2, float* __restrict__ out, int n) {
    int t = blockIdx.x * blockDim.x + threadIdx.x;
    int node = t >> 4;
    if (node >= n) return;
    int c = t & 15;

    int beg = g_rowptr[node], end = g_rowptr[node + 1];
    float4 s = make_float4(0.f, 0.f, 0.f, 0.f);
    const float4* p4 = reinterpret_cast<const float4*>(g_p);
    for (int e = beg; e < end; e++) {
        int src = g_eidx[e];
        float4 v = p4[(size_t)src * 16 + c];
        s.x += v.x; s.y += v.y; s.z += v.z; s.w += v.w;
    }
    float  r = g_rdeg[node];
    float4 q = reinterpret_cast<const float4*>(g_q)[(size_t)node * 16 + c];
    float4 b = reinterpret_cast<const float4*>(b2)[c];
    float4 o;
    o.x = s.x * r + b.x + q.x;
    o.y = s.y * r + b.y + q.y;
    o.z = s.z * r + b.z + q.z;
    o.w = s.w * r + b.w + q.w;
    reinterpret_cast<float4*>(out)[(size_t)node * 16 + c] = o;
}

// ============================================================
extern "C" void kernel_launch(void* const* d_in, const int* in_sizes, int n_in,
                              void* d_out, int out_size) {
    const float* x    = (const float*)d_in[0];
    const int*   ei32 = (const int*)d_in[1];     // int32 view; dtype detected on device
    const float* W1l  = (const float*)d_in[2];
    const float* b1   = (const float*)d_in[3];
    const float* W1r  = (const float*)d_in[4];
    const float* W2l  = (const float*)d_in[5];
    const float* b2   = (const float*)d_in[6];
    const float* W2r  = (const float*)d_in[7];
    float*       out  = (float*)d_out;

    int N = in_sizes[0] / F1;          // 50000
    int E = in_sizes[1] / 2;           // 800000

    // edge dtype detect + normalize + zero histogram
    k_detect <<<1, 32>>>(ei32);
    {
        int tot = (E > N) ? E : N;
        k_convert<<<(tot + 255) / 256, 256>>>(ei32, E, N);
    }

    // CSR build (int atomics only)
    k_hist<<<(E + 255) / 256, 256>>>(E);
    k_scan<<<1, 1024>>>(N);
    k_bin <<<(E + 255) / 256, 256>>>(E);

    // layer 1
    k_agg1 <<<(N * 32 + 255) / 256, 256>>>(x, N);
    k_gemm1<<<(N + 127) / 128, 256>>>(x, W1l, b1, W1r, N);

    // layer 2
    k_gemm2   <<<(N + 127) / 128, 256>>>(W2l, W2r, N);
    k_aggfinal<<<(N * 16 + 255) / 256, 256>>>(b2, out, N);
}